// round 12
// baseline (speedup 1.0000x reference)
#include <cuda_runtime.h>
#include <cstdint>
#include <math.h>

// Problem constants
#define TT 512
#define BB 8
#define DD 512
#define NN 64

// Scratch (allocation-free rule: __device__ globals)
__device__ float g_k[TT * BB * DD];
__device__ float g_q[TT * BB * DD];
__device__ float g_wx[TT * BB * NN];     // W_x @ x + b
__device__ float g_alpha[TT * BB * NN];  // sigmoid(W_alpha @ x + b_alpha)
__device__ float g_c2[TT * BB * NN];     // (1 - alpha) * v  (recur -> scan)

// ---------------------------------------------------------------------------
// Fast tanh: tanh(x) = 1 - 2/(1 + e^{2x})  (MUFU ex2 + rcp; abs err ~1e-7)
// ---------------------------------------------------------------------------
__device__ __forceinline__ float fast_tanh(float x) {
    float e;
    asm("ex2.approx.f32 %0, %1;" : "=f"(e) : "f"(x * 2.8853900817779268f));
    float r;
    asm("rcp.approx.f32 %0, %1;" : "=f"(r) : "f"(e + 1.0f));
    return fmaf(-2.0f, r, 1.0f);
}

__device__ __forceinline__ float dot4(const float4 a, const float4 b) {
    return fmaf(a.x, b.x, fmaf(a.y, b.y, fmaf(a.z, b.z, a.w * b.w)));
}
__device__ __forceinline__ float warp_sum(float v) {
    v += __shfl_xor_sync(0xffffffffu, v, 16);
    v += __shfl_xor_sync(0xffffffffu, v, 8);
    v += __shfl_xor_sync(0xffffffffu, v, 4);
    v += __shfl_xor_sync(0xffffffffu, v, 2);
    v += __shfl_xor_sync(0xffffffffu, v, 1);
    return v;
}

// ============================================================================
// Kernel 1: fused projection GEMM (unchanged — passing)
// ============================================================================
#define PM 4096
#define PK 512
#define PN 1152
#define TBM 128
#define TBN 128
#define TBK 16

__global__ __launch_bounds__(256) void proj_kernel(
    const float* __restrict__ x,
    const float* __restrict__ Wk, const float* __restrict__ Wq,
    const float* __restrict__ Wx, const float* __restrict__ Wa,
    const float* __restrict__ bvec, const float* __restrict__ ba)
{
    __shared__ float As[TBK][TBM + 4];
    __shared__ float Bs[TBK][TBN + 4];

    const int tid = threadIdx.x;
    const int tx = tid & 15;
    const int ty = tid >> 4;
    const int m0 = blockIdx.x * TBM;
    const int n0 = blockIdx.y * TBN;

    const int kq = tid & 3;
    const int r0 = tid >> 2;

    const float* wr0p;
    const float* wr1p;
    {
        int jg = n0 + r0;
        wr0p = (jg < 512) ? Wk + (size_t)jg * 512
             : (jg < 1024) ? Wq + (size_t)(jg - 512) * 512
             : (jg < 1088) ? Wx + (size_t)(jg - 1024) * 512
                           : Wa + (size_t)(jg - 1088) * 512;
        jg = n0 + r0 + 64;
        wr1p = (jg < 512) ? Wk + (size_t)jg * 512
             : (jg < 1024) ? Wq + (size_t)(jg - 512) * 512
             : (jg < 1088) ? Wx + (size_t)(jg - 1024) * 512
                           : Wa + (size_t)(jg - 1088) * 512;
    }
    const float* xr0 = x + (size_t)(m0 + r0) * PK;
    const float* xr1 = x + (size_t)(m0 + r0 + 64) * PK;

    float acc[8][8];
#pragma unroll
    for (int i = 0; i < 8; i++)
#pragma unroll
        for (int j = 0; j < 8; j++) acc[i][j] = 0.0f;

    for (int kt = 0; kt < PK; kt += TBK) {
        float4 a0 = *(const float4*)(xr0 + kt + kq * 4);
        float4 a1 = *(const float4*)(xr1 + kt + kq * 4);
        float4 b0 = *(const float4*)(wr0p + kt + kq * 4);
        float4 b1 = *(const float4*)(wr1p + kt + kq * 4);

        As[kq * 4 + 0][r0] = a0.x; As[kq * 4 + 1][r0] = a0.y;
        As[kq * 4 + 2][r0] = a0.z; As[kq * 4 + 3][r0] = a0.w;
        As[kq * 4 + 0][r0 + 64] = a1.x; As[kq * 4 + 1][r0 + 64] = a1.y;
        As[kq * 4 + 2][r0 + 64] = a1.z; As[kq * 4 + 3][r0 + 64] = a1.w;

        Bs[kq * 4 + 0][r0] = b0.x; Bs[kq * 4 + 1][r0] = b0.y;
        Bs[kq * 4 + 2][r0] = b0.z; Bs[kq * 4 + 3][r0] = b0.w;
        Bs[kq * 4 + 0][r0 + 64] = b1.x; Bs[kq * 4 + 1][r0 + 64] = b1.y;
        Bs[kq * 4 + 2][r0 + 64] = b1.z; Bs[kq * 4 + 3][r0 + 64] = b1.w;

        __syncthreads();

#pragma unroll
        for (int kk = 0; kk < TBK; kk++) {
            float a[8], bq[8];
            *(float4*)&a[0]  = *(const float4*)&As[kk][ty * 8];
            *(float4*)&a[4]  = *(const float4*)&As[kk][ty * 8 + 4];
            *(float4*)&bq[0] = *(const float4*)&Bs[kk][tx * 8];
            *(float4*)&bq[4] = *(const float4*)&Bs[kk][tx * 8 + 4];
#pragma unroll
            for (int i = 0; i < 8; i++)
#pragma unroll
                for (int j = 0; j < 8; j++)
                    acc[i][j] = fmaf(a[i], bq[j], acc[i][j]);
        }
        __syncthreads();
    }

    const int c0 = n0 + tx * 8;
    if (c0 < 512) {
#pragma unroll
        for (int i = 0; i < 8; i++) {
            int r = m0 + ty * 8 + i;
            float* base = g_k + (size_t)r * DD + c0;
            *(float4*)(base)     = make_float4(acc[i][0], acc[i][1], acc[i][2], acc[i][3]);
            *(float4*)(base + 4) = make_float4(acc[i][4], acc[i][5], acc[i][6], acc[i][7]);
        }
    } else if (c0 < 1024) {
#pragma unroll
        for (int i = 0; i < 8; i++) {
            int r = m0 + ty * 8 + i;
            float* base = g_q + (size_t)r * DD + (c0 - 512);
            *(float4*)(base)     = make_float4(acc[i][0], acc[i][1], acc[i][2], acc[i][3]);
            *(float4*)(base + 4) = make_float4(acc[i][4], acc[i][5], acc[i][6], acc[i][7]);
        }
    } else if (c0 < 1088) {
        const int cc = c0 - 1024;
        float bb[8];
#pragma unroll
        for (int j = 0; j < 8; j++) bb[j] = bvec[cc + j];
#pragma unroll
        for (int i = 0; i < 8; i++) {
            int r = m0 + ty * 8 + i;
            float* base = g_wx + (size_t)r * NN + cc;
#pragma unroll
            for (int j = 0; j < 8; j++) base[j] = acc[i][j] + bb[j];
        }
    } else {
        const int cc = c0 - 1088;
        float bb[8];
#pragma unroll
        for (int j = 0; j < 8; j++) bb[j] = ba[cc + j];
#pragma unroll
        for (int i = 0; i < 8; i++) {
            int r = m0 + ty * 8 + i;
            float* base = g_alpha + (size_t)r * NN + cc;
#pragma unroll
            for (int j = 0; j < 8; j++)
                base[j] = 1.0f / (1.0f + expf(-(acc[i][j] + bb[j])));
        }
    }
}

// ============================================================================
// Kernel 2: serial recurrence — ONE CTA per batch (8 CTAs x 512 threads).
// Warp w owns rows n = 4w..4w+3; lane owns d in [16*lane, 16*lane+16).
// Exchange = local SMEM + one __syncthreads per step. Emits only c2[t,b,n].
// v-matvec: lane l handles row (l>>3), m in [8*(l&7), +8) -> 3-shfl reduce.
// k(t+1) staged in double-buffered smem via cp.async (warps 0-3).
// ============================================================================
__global__ void __launch_bounds__(512, 1)
recur_kernel(const float* __restrict__ S0, const float* __restrict__ Wr)
{
    const int b    = blockIdx.x;
    const int tid  = threadIdx.x;
    const int w    = tid >> 5;
    const int lane = tid & 31;
    const int grp  = lane >> 3;          // 0..3  (row within warp for v-matvec)
    const int gl   = lane & 7;           // lane within 8-lane group
    const int nv   = w * 4 + grp;        // row this lane reduces v for
    const int m0   = gl * 8;             // W_r column block for v partial

    __shared__ float rbuf[2][NN];
    __shared__ float ksm[2][DD];

    // W_r fragment for the v-matvec: Wr[nv][m0 .. m0+7]
    float4 wrA = *(const float4*)(Wr + nv * NN + m0);
    float4 wrB = *(const float4*)(Wr + nv * NN + m0 + 4);

    // State S: 4 rows x 16 d in registers
    float4 s[4][4];
#pragma unroll
    for (int i = 0; i < 4; i++) {
        const float4* p = (const float4*)(S0 + (size_t)(b * NN + w * 4 + i) * DD + lane * 16);
#pragma unroll
        for (int j = 0; j < 4; j++) s[i][j] = p[j];
    }

    // k(0) direct load
    float4 kv[4];
    {
        const float4* p = (const float4*)(g_k + (size_t)b * DD + lane * 16);
#pragma unroll
        for (int j = 0; j < 4; j++) kv[j] = p[j];
    }

    // Stage k(1) -> ksm[1] via cp.async (warps 0-3: 16B per lane)
    if (w < 4) {
        uint32_t dst = (uint32_t)__cvta_generic_to_shared(&ksm[1][w * 128 + lane * 4]);
        const float* src = g_k + (size_t)1 * BB * DD + (size_t)b * DD + w * 128 + lane * 4;
        asm volatile("cp.async.cg.shared.global [%0], [%1], 16;" :: "r"(dst), "l"(src) : "memory");
        asm volatile("cp.async.commit_group;" ::: "memory");
    }

    // wx(0), alpha(0) for this lane's row nv
    float wxc = __ldg(g_wx + b * NN + nv);
    float alc = __ldg(g_alpha + b * NN + nv);

    // A_i(0) = S0 . k(0)  (4 full-warp reductions)
    float A0, A1, A2, A3;
    {
        float a0 = dot4(s[0][0], kv[0]) + dot4(s[0][1], kv[1]) + dot4(s[0][2], kv[2]) + dot4(s[0][3], kv[3]);
        float a1 = dot4(s[1][0], kv[0]) + dot4(s[1][1], kv[1]) + dot4(s[1][2], kv[2]) + dot4(s[1][3], kv[3]);
        float a2 = dot4(s[2][0], kv[0]) + dot4(s[2][1], kv[1]) + dot4(s[2][2], kv[2]) + dot4(s[2][3], kv[3]);
        float a3 = dot4(s[3][0], kv[0]) + dot4(s[3][1], kv[1]) + dot4(s[3][2], kv[2]) + dot4(s[3][3], kv[3]);
#pragma unroll
        for (int off = 16; off >= 1; off >>= 1) {
            a0 += __shfl_xor_sync(0xffffffffu, a0, off);
            a1 += __shfl_xor_sync(0xffffffffu, a1, off);
            a2 += __shfl_xor_sync(0xffffffffu, a2, off);
            a3 += __shfl_xor_sync(0xffffffffu, a3, off);
        }
        A0 = a0; A1 = a1; A2 = a2; A3 = a3;
    }

    float* c2out = g_c2 + b * NN + nv;

    for (int t = 0; t < TT; t++) {
        const int ib = t & 1;

        // r = tanh(A) -> rbuf (lane0 stores the warp's 4 rows)
        if (lane == 0) {
            *(float4*)&rbuf[ib][w * 4] =
                make_float4(fast_tanh(A0), fast_tanh(A1), fast_tanh(A2), fast_tanh(A3));
        }
        // ensure k(t+1) landed before anyone reads ksm this step
        if (w < 4) asm volatile("cp.async.wait_group 0;" ::: "memory");
        __syncthreads();

        // ---- v-matvec: pv = sum_m Wr[nv][m] r[m] over this lane's 8 m's ----
        float4 rA = *(const float4*)&rbuf[ib][m0];
        float4 rB = *(const float4*)&rbuf[ib][m0 + 4];
        float pv = dot4(rA, wrA) + dot4(rB, wrB);
        pv += __shfl_xor_sync(0xffffffffu, pv, 1);
        pv += __shfl_xor_sync(0xffffffffu, pv, 2);
        pv += __shfl_xor_sync(0xffffffffu, pv, 4);
        float v  = fast_tanh(pv + wxc);
        float c2 = (1.0f - alc) * v;

        // emit c2 for this row (one lane per group)
        if (gl == 0) c2out[(size_t)t * BB * NN] = c2;

        // broadcast c2/alpha for the warp's 4 update rows
        float c2r[4], alr[4];
#pragma unroll
        for (int i = 0; i < 4; i++) {
            c2r[i] = __shfl_sync(0xffffffffu, c2,  i * 8);
            alr[i] = __shfl_sync(0xffffffffu, alc, i * 8);
        }

        // prefetch wx/alpha(t+1)
        const int tn = (t < TT - 1) ? t + 1 : t;
        float wxn = __ldg(g_wx + (size_t)tn * BB * NN + b * NN + nv);
        float aln = __ldg(g_alpha + (size_t)tn * BB * NN + b * NN + nv);

        // stage k(t+2) -> ksm[t&1]
        if (w < 4) {
            const int t2 = (t + 2 < TT) ? t + 2 : TT - 1;
            uint32_t dst = (uint32_t)__cvta_generic_to_shared(&ksm[ib][w * 128 + lane * 4]);
            const float* src = g_k + (size_t)t2 * BB * DD + (size_t)b * DD + w * 128 + lane * 4;
            asm volatile("cp.async.cg.shared.global [%0], [%1], 16;" :: "r"(dst), "l"(src) : "memory");
            asm volatile("cp.async.commit_group;" ::: "memory");
        }

        // k(t+1) from smem
        float4 kn[4];
#pragma unroll
        for (int j = 0; j < 4; j++)
            kn[j] = *(const float4*)&ksm[1 - ib][lane * 16 + j * 4];

        // fused update + next-step dot:  s = al*s + c2*k ;  A_next = s . k(t+1)
        float a0 = 0.f, a1 = 0.f, a2 = 0.f, a3 = 0.f;
#pragma unroll
        for (int j = 0; j < 4; j++) {
            s[0][j].x = fmaf(alr[0], s[0][j].x, c2r[0] * kv[j].x);
            s[0][j].y = fmaf(alr[0], s[0][j].y, c2r[0] * kv[j].y);
            s[0][j].z = fmaf(alr[0], s[0][j].z, c2r[0] * kv[j].z);
            s[0][j].w = fmaf(alr[0], s[0][j].w, c2r[0] * kv[j].w);
            a0 += dot4(s[0][j], kn[j]);
            s[1][j].x = fmaf(alr[1], s[1][j].x, c2r[1] * kv[j].x);
            s[1][j].y = fmaf(alr[1], s[1][j].y, c2r[1] * kv[j].y);
            s[1][j].z = fmaf(alr[1], s[1][j].z, c2r[1] * kv[j].z);
            s[1][j].w = fmaf(alr[1], s[1][j].w, c2r[1] * kv[j].w);
            a1 += dot4(s[1][j], kn[j]);
            s[2][j].x = fmaf(alr[2], s[2][j].x, c2r[2] * kv[j].x);
            s[2][j].y = fmaf(alr[2], s[2][j].y, c2r[2] * kv[j].y);
            s[2][j].z = fmaf(alr[2], s[2][j].z, c2r[2] * kv[j].z);
            s[2][j].w = fmaf(alr[2], s[2][j].w, c2r[2] * kv[j].w);
            a2 += dot4(s[2][j], kn[j]);
            s[3][j].x = fmaf(alr[3], s[3][j].x, c2r[3] * kv[j].x);
            s[3][j].y = fmaf(alr[3], s[3][j].y, c2r[3] * kv[j].y);
            s[3][j].z = fmaf(alr[3], s[3][j].z, c2r[3] * kv[j].z);
            s[3][j].w = fmaf(alr[3], s[3][j].w, c2r[3] * kv[j].w);
            a3 += dot4(s[3][j], kn[j]);
        }
#pragma unroll
        for (int off = 16; off >= 1; off >>= 1) {
            a0 += __shfl_xor_sync(0xffffffffu, a0, off);
            a1 += __shfl_xor_sync(0xffffffffu, a1, off);
            a2 += __shfl_xor_sync(0xffffffffu, a2, off);
            a3 += __shfl_xor_sync(0xffffffffu, a3, off);
        }
        A0 = a0; A1 = a1; A2 = a2; A3 = a3;

#pragma unroll
        for (int j = 0; j < 4; j++) kv[j] = kn[j];
        wxc = wxn; alc = aln;
    }
}

// ============================================================================
// Kernel 3: parallel scan — replay S and compute y across all SMs.
// One warp per (b, n): lane owns 16 d's. S = al*S + c2*k each step; stream S
// to d_out; y[t] = tanh(S . q(t)). DRAM-write-bound (~537 MB).
// ============================================================================
__global__ void __launch_bounds__(128) scan_kernel(
    const float* __restrict__ S0, float* __restrict__ out)
{
    const int gw   = blockIdx.x * 4 + (threadIdx.x >> 5);  // 0..511
    const int lane = threadIdx.x & 31;
    const int b    = gw >> 6;
    const int n    = gw & 63;

    float* out_y = out;                            // [T,B,N]
    float* out_S = out + (size_t)TT * BB * NN;     // [T+1,B,N,D]

    // Load S0 slice, emit S[0]
    float4 s0_, s1_, s2_, s3_;
    {
        const float4* p = (const float4*)(S0 + (size_t)(b * NN + n) * DD + lane * 16);
        s0_ = p[0]; s1_ = p[1]; s2_ = p[2]; s3_ = p[3];
        float4* o = (float4*)(out_S + (size_t)(b * NN + n) * DD + lane * 16);
        o[0] = s0_; o[1] = s1_; o[2] = s2_; o[3] = s3_;
    }

    const float* kp = g_k + b * DD + lane * 16;
    const float* qp = g_q + b * DD + lane * 16;
    const float* cp = g_c2 + b * NN + n;
    const float* ap = g_alpha + b * NN + n;
    float* yp = out_y + b * NN + n;
    float* sp = out_S + (size_t)((BB + b) * NN + n) * DD + lane * 16;

    // prime t=0
    float4 k0 = *(const float4*)(kp);     float4 k1 = *(const float4*)(kp + 4);
    float4 k2 = *(const float4*)(kp + 8); float4 k3 = *(const float4*)(kp + 12);
    float4 q0 = *(const float4*)(qp);     float4 q1 = *(const float4*)(qp + 4);
    float4 q2 = *(const float4*)(qp + 8); float4 q3 = *(const float4*)(qp + 12);
    float c2 = __ldg(cp);
    float al = __ldg(ap);

    for (int t = 0; t < TT; t++) {
        // prefetch next step
        const int adv  = (t < TT - 1) ? BB * DD : 0;
        const int advn = (t < TT - 1) ? BB * NN : 0;
        float4 nk0 = *(const float4*)(kp + adv);     float4 nk1 = *(const float4*)(kp + adv + 4);
        float4 nk2 = *(const float4*)(kp + adv + 8); float4 nk3 = *(const float4*)(kp + adv + 12);
        float4 nq0 = *(const float4*)(qp + adv);     float4 nq1 = *(const float4*)(qp + adv + 4);
        float4 nq2 = *(const float4*)(qp + adv + 8); float4 nq3 = *(const float4*)(qp + adv + 12);
        float nc2 = __ldg(cp + advn);
        float nal = __ldg(ap + advn);

        // S = al*S + c2*k
        s0_.x = fmaf(al, s0_.x, c2 * k0.x); s0_.y = fmaf(al, s0_.y, c2 * k0.y);
        s0_.z = fmaf(al, s0_.z, c2 * k0.z); s0_.w = fmaf(al, s0_.w, c2 * k0.w);
        s1_.x = fmaf(al, s1_.x, c2 * k1.x); s1_.y = fmaf(al, s1_.y, c2 * k1.y);
        s1_.z = fmaf(al, s1_.z, c2 * k1.z); s1_.w = fmaf(al, s1_.w, c2 * k1.w);
        s2_.x = fmaf(al, s2_.x, c2 * k2.x); s2_.y = fmaf(al, s2_.y, c2 * k2.y);
        s2_.z = fmaf(al, s2_.z, c2 * k2.z); s2_.w = fmaf(al, s2_.w, c2 * k2.w);
        s3_.x = fmaf(al, s3_.x, c2 * k3.x); s3_.y = fmaf(al, s3_.y, c2 * k3.y);
        s3_.z = fmaf(al, s3_.z, c2 * k3.z); s3_.w = fmaf(al, s3_.w, c2 * k3.w);

        __stcs((float4*)sp + 0, s0_);
        __stcs((float4*)sp + 1, s1_);
        __stcs((float4*)sp + 2, s2_);
        __stcs((float4*)sp + 3, s3_);

        // y = tanh(S . q)
        float y = dot4(s0_, q0) + dot4(s1_, q1) + dot4(s2_, q2) + dot4(s3_, q3);
        y = warp_sum(y);
        if (lane == 0) *yp = fast_tanh(y);

        k0 = nk0; k1 = nk1; k2 = nk2; k3 = nk3;
        q0 = nq0; q1 = nq1; q2 = nq2; q3 = nq3;
        c2 = nc2; al = nal;
        kp += BB * DD; qp += BB * DD; cp += BB * NN; ap += BB * NN;
        yp += BB * NN; sp += (size_t)BB * NN * DD;
    }
}

// ============================================================================
// Launch: proj -> recur (serial, tiny output) -> scan (parallel, big output)
//   inputs: x, S0, W_k, W_q, W_x, W_r, b, W_alpha, b_alpha
//   output: concat( y[T,B,N], S[T+1,B,N,D] )  fp32
// ============================================================================
extern "C" void kernel_launch(void* const* d_in, const int* in_sizes, int n_in,
                              void* d_out, int out_size)
{
    const float* x   = (const float*)d_in[0];
    const float* S0  = (const float*)d_in[1];
    const float* Wk  = (const float*)d_in[2];
    const float* Wq  = (const float*)d_in[3];
    const float* Wx  = (const float*)d_in[4];
    const float* Wr  = (const float*)d_in[5];
    const float* bv  = (const float*)d_in[6];
    const float* Wa  = (const float*)d_in[7];
    const float* ba  = (const float*)d_in[8];
    float* out = (float*)d_out;

    dim3 pg(PM / TBM, PN / TBN);   // (32, 9)
    proj_kernel<<<pg, 256>>>(x, Wk, Wq, Wx, Wa, bv, ba);

    recur_kernel<<<BB, 512>>>(S0, Wr);

    scan_kernel<<<128, 128>>>(S0, out);
}